// round 9
// baseline (speedup 1.0000x reference)
#include <cuda_runtime.h>

typedef unsigned long long ULL;

// ---------------- device scratch (no allocations allowed) ----------------
// Stage-1 partial sums: [b][s][idx]  (b:256, s:16, idx:320 = (c*10+w)*2+comp)
__device__ float fpart_g[256 * 16 * 320];
// Pre-batchnorm output: [b][c*2+o]
__device__ float out_g[256 * 32];

// ---------------- packed f32x2 FMA (FFMA2) ----------------
__device__ __forceinline__ ULL fma2(ULL a, ULL b, ULL c) {
    ULL d;
    asm("fma.rn.f32x2 %0, %1, %2, %3;" : "=l"(d) : "l"(a), "l"(b), "l"(c));
    return d;
}

// ---------------- kernel 1: depthwise sliding filters (stage 1) ----------------
// grid (256 batches, 16 segments), 256 threads = 16 channels x 16 j-chunks.
// Each thread: 16 positions (two batched groups of 8 x-loads for MLP), then a
// block smem reduction over the 16 j-chunks.
// f[b,w,c] = sum_p x[b,p,c] * Wpad[p - w + 9],  Wpad[lp] = W[lp-9] (zero-pad)
__global__ void __launch_bounds__(256) stage1_kernel(const float* __restrict__ x,
                                                     const float* __restrict__ wr,
                                                     const float* __restrict__ wi) {
    __shared__ __align__(16) ULL ws[265 * 16];       // 33.9KB: ws[i][c] = Wpad[ps+i]
    float (*red)[322] = (float (*)[322])ws;          // reuse after compute (20.6KB)

    int b   = blockIdx.x;
    int s   = blockIdx.y;
    int tid = threadIdx.x;
    int c   = tid & 15;
    int j   = tid >> 4;          // 0..15
    int pl  = j * 16;            // local position start
    int ps  = s * 256;           // global segment start

    // cooperative weight gather with zero-pad: ws[i*16+cc] = {wr[cc][l], wi[cc][l]},
    // l = ps + i - 9  (ws[i] = Wpad[ps+i])
    {
        int cc = tid >> 4;
        for (int i = tid & 15; i < 265; i += 16) {
            int l = ps + i - 9;
            float a = 0.f, bb = 0.f;
            if (l >= 0 && l < 4087) {
                a  = wr[cc * 4087 + l];
                bb = wi[cc * 4087 + l];
            }
            float2 v = make_float2(a, bb);
            ws[i * 16 + cc] = *(ULL*)&v;
        }
    }
    __syncthreads();

    const ULL* xp = (const ULL*)x + ((size_t)b * 4096 + ps + pl) * 16 + c;

    // rotating window over local index m = t + 9 - w (0..24): slot = m % 10,
    // slot holds ws[pl + m]. Preload m = 0..8.
    ULL wbuf[10];
#pragma unroll
    for (int k = 0; k < 9; k++) wbuf[k] = ws[(pl + k) * 16 + c];

    ULL acc[10];
#pragma unroll
    for (int w = 0; w < 10; w++) acc[w] = 0ULL;

#pragma unroll
    for (int g = 0; g < 2; g++) {
        ULL xv[8];
#pragma unroll
        for (int u = 0; u < 8; u++) xv[u] = xp[(size_t)(g * 8 + u) * 16];
#pragma unroll
        for (int u = 0; u < 8; u++) {
            int t = g * 8 + u;
            wbuf[(t + 9) % 10] = ws[(pl + t + 9) * 16 + c];
#pragma unroll
            for (int w = 0; w < 10; w++)
                acc[w] = fma2(xv[u], wbuf[(t + 9 - w) % 10], acc[w]);
        }
    }
    __syncthreads();   // done reading ws; reuse as red

    // dump partials: red[j][(c*10+w)*2+comp]
#pragma unroll
    for (int w = 0; w < 10; w++) {
        red[j][(c * 10 + w) * 2 + 0] = __uint_as_float((unsigned)(acc[w] & 0xffffffffULL));
        red[j][(c * 10 + w) * 2 + 1] = __uint_as_float((unsigned)(acc[w] >> 32));
    }
    __syncthreads();

    // reduce 16 j-chunks over 320 entries (256 threads, strided)
    for (int idx = tid; idx < 320; idx += 256) {
        float v = 0.f;
#pragma unroll
        for (int jj = 0; jj < 16; jj++) v += red[jj][idx];
        fpart_g[((size_t)b * 16 + s) * 320 + idx] = v;
    }
}

// ---------------- kernel 2: amp + Linear(2C->2) + out filter ----------------
// one block per b, 512 threads. Stage the 20KB fpart slice into smem (float4),
// reduce over s from smem. Writes pre-BN out_g.
__global__ void __launch_bounds__(512) stage23_kernel(const float* __restrict__ Wnl,
                                                      const float* __restrict__ WoR,
                                                      const float* __restrict__ WoI) {
    __shared__ __align__(16) float sbuf[5120];    // 20KB staging
    __shared__ float tf[10][32];       // [w][i], i<16: amp*fr, i>=16: amp*fi
    __shared__ float contrib[10][32];  // [w][c*2+o]

    int b = blockIdx.x;
    int tid = threadIdx.x;

    // bulk stage fpart[b] (5120 floats = 1280 float4) into smem
    {
        const float4* src4 = (const float4*)(fpart_g + (size_t)b * 5120);
        float4* dst4 = (float4*)sbuf;
        if (tid < 256) {
#pragma unroll
            for (int i = 0; i < 5; i++) dst4[tid + i * 256] = src4[tid + i * 256];
        }
    }
    __syncthreads();

    // reduce over s from smem; idx = (c*10+w)*2+o = tid
    if (tid < 320) {
        float v = 0.f;
#pragma unroll
        for (int s = 0; s < 16; s++) v += sbuf[s * 320 + tid];
        float other = __shfl_xor_sync(0xffffffffu, v, 1);
        float amp = v * v + other * other;
        int pair = tid >> 1;          // c*10 + w
        int o    = tid & 1;
        int c    = pair / 10;
        int w    = pair - c * 10;
        tf[w][c + 16 * o] = amp * v;  // o=0: amp*fr ; o=1: amp*fi
    }
    __syncthreads();

    // Linear(2C->2) + output-filter weighting
    if (tid < 320) {
        int w = tid >> 5;
        int q = tid & 31;
        int c = q >> 1;
        int o = q & 1;
        float acc = 0.f;
        const float* wn = Wnl + (c * 2 + o) * 32;
#pragma unroll
        for (int i = 0; i < 32; i++) acc += tf[w][i] * wn[i];
        float wo = (o == 0 ? WoR : WoI)[c * 10 + w];
        contrib[w][q] = acc * wo;
    }
    __syncthreads();

    // sum over w, write pre-BN output
    if (tid < 32) {
        float ssum = 0.f;
#pragma unroll
        for (int ww = 0; ww < 10; ww++) ssum += contrib[ww][tid];
        out_g[b * 32 + tid] = ssum;
    }
}

// ---------------- kernel 3: BatchNorm1d (training stats), 1 block ----------------
__global__ void __launch_bounds__(512) bn_kernel(const float* __restrict__ gamma,
                                                 const float* __restrict__ beta,
                                                 float* __restrict__ out) {
    __shared__ float bnbuf[32][257];   // [q = ch*2+o][b], padded rows

    int tid = threadIdx.x;
    for (int i = tid; i < 8192; i += 512) {
        int bb = i >> 5;
        int q  = i & 31;
        bnbuf[q][bb] = out_g[i];
    }
    __syncthreads();

    // one warp per channel
    int ch = tid >> 5, lane = tid & 31;
    float s1 = 0.f;
#pragma unroll
    for (int j = 0; j < 8; j++) {
        int bb = lane + j * 32;
        s1 += bnbuf[2 * ch][bb] + bnbuf[2 * ch + 1][bb];
    }
#pragma unroll
    for (int off = 16; off; off >>= 1) s1 += __shfl_xor_sync(0xffffffffu, s1, off);
    float mean = s1 * (1.f / 512.f);

    float s2 = 0.f;
#pragma unroll
    for (int j = 0; j < 8; j++) {
        int bb = lane + j * 32;
        float d0 = bnbuf[2 * ch][bb] - mean;
        float d1 = bnbuf[2 * ch + 1][bb] - mean;
        s2 += d0 * d0 + d1 * d1;
    }
#pragma unroll
    for (int off = 16; off; off >>= 1) s2 += __shfl_xor_sync(0xffffffffu, s2, off);
    float inv = rsqrtf(s2 * (1.f / 512.f) + 1e-5f);

    float g = gamma[ch], bb_ = beta[ch];
#pragma unroll
    for (int j = 0; j < 8; j++) {
        int bb = lane + j * 32;
        out[bb * 32 + 2 * ch]     = (bnbuf[2 * ch][bb] - mean) * inv * g + bb_;
        out[bb * 32 + 2 * ch + 1] = (bnbuf[2 * ch + 1][bb] - mean) * inv * g + bb_;
    }
}

// ---------------- launch ----------------
extern "C" void kernel_launch(void* const* d_in, const int* in_sizes, int n_in,
                              void* d_out, int out_size) {
    const float* x     = (const float*)d_in[0];
    const float* wir   = (const float*)d_in[1];
    const float* wii   = (const float*)d_in[2];
    const float* wnl   = (const float*)d_in[3];
    const float* wor   = (const float*)d_in[4];
    const float* woi   = (const float*)d_in[5];
    const float* gamma = (const float*)d_in[6];
    const float* beta  = (const float*)d_in[7];
    float* out = (float*)d_out;

    stage1_kernel<<<dim3(256, 16), 256>>>(x, wir, wii);
    stage23_kernel<<<256, 512>>>(wnl, wor, woi);
    bn_kernel<<<1, 512>>>(gamma, beta, out);
}

// round 10
// speedup vs baseline: 1.7516x; 1.7516x over previous
#include <cuda_runtime.h>

typedef unsigned long long ULL;

// ---------------- device scratch (no allocations allowed) ----------------
// Stage-1 partial sums: [b][s][idx]  (b:256, s:16, idx:320 = (c*10+w)*2+comp)
__device__ float fpart_g[256 * 16 * 320];
// Pre-batchnorm output: [b][c*2+o]
__device__ float out_g[256 * 32];

// ---------------- packed f32x2 FMA (FFMA2) ----------------
__device__ __forceinline__ ULL fma2(ULL a, ULL b, ULL c) {
    ULL d;
    asm("fma.rn.f32x2 %0, %1, %2, %3;" : "=l"(d) : "l"(a), "l"(b), "l"(c));
    return d;
}
__device__ __forceinline__ float2 u2f2(ULL v) {
    return make_float2(__uint_as_float((unsigned)(v & 0xffffffffULL)),
                       __uint_as_float((unsigned)(v >> 32)));
}

// ---------------- kernel 1: depthwise sliding filters (stage 1) ----------------
// grid (64 batch-groups, 16 segments), 256 threads = 16 channels x 16 j-chunks.
// One weight-slice gather per block (conflict-free, pad-17 rows), amortized
// over 4 serially-processed batches. Per batch: 16 positions per thread with
// two batched groups of 8 x-loads (MLP 8), warp shfl j-pair combine, then an
// 8-row smem reduction.
// f[b,w,c] = sum_p x[b,p,c] * Wpad[p - w + 9],  Wpad[lp] = W[lp-9] (zero-pad)
__global__ void __launch_bounds__(256) stage1_kernel(const float* __restrict__ x,
                                                     const float* __restrict__ wr,
                                                     const float* __restrict__ wi) {
    __shared__ __align__(16) ULL ws[265 * 17];     // 36.0KB, rows padded to 17
    __shared__ float red[8][320];                  // 10.2KB, per-warp partials

    int bg  = blockIdx.x;        // 0..63
    int s   = blockIdx.y;        // 0..15
    int tid = threadIdx.x;
    int c   = tid & 15;
    int j   = tid >> 4;          // 0..15
    int pl  = j * 16;            // local position start
    int ps  = s * 256;           // global segment start
    int warp = tid >> 5;         // 0..7

    // conflict-free weight gather: thread (cc = tid>>4, i = tid&15 step 16).
    // LDG: 16 consecutive l per cc (coalesced). STS: ws[i*17+cc] -> banks
    // (i*34 + 2cc) mod 32, distinct within each 16-lane phase.
    {
        int cc = tid >> 4;
        for (int i = tid & 15; i < 265; i += 16) {
            int l = ps + i - 9;
            float a = 0.f, b2 = 0.f;
            if (l >= 0 && l < 4087) {
                a  = wr[cc * 4087 + l];
                b2 = wi[cc * 4087 + l];
            }
            float2 v = make_float2(a, b2);
            ws[i * 17 + cc] = *(ULL*)&v;
        }
    }
    __syncthreads();

    // 4 batches share the staged weights
    for (int g = 0; g < 4; g++) {
        int b = bg * 4 + g;
        const ULL* xp = (const ULL*)x + ((size_t)b * 4096 + ps + pl) * 16 + c;

        // rotating window: slot = m % 10 holds ws[pl + m]; preload m = 0..8
        ULL wbuf[10];
#pragma unroll
        for (int k = 0; k < 9; k++) wbuf[k] = ws[(pl + k) * 17 + c];

        ULL acc[10];
#pragma unroll
        for (int w = 0; w < 10; w++) acc[w] = 0ULL;

#pragma unroll
        for (int gg = 0; gg < 2; gg++) {
            ULL xv[8];
#pragma unroll
            for (int u = 0; u < 8; u++) xv[u] = xp[(size_t)(gg * 8 + u) * 16];
#pragma unroll
            for (int u = 0; u < 8; u++) {
                int t = gg * 8 + u;
                wbuf[(t + 9) % 10] = ws[(pl + t + 9) * 17 + c];
#pragma unroll
                for (int w = 0; w < 10; w++)
                    acc[w] = fma2(xv[u], wbuf[(t + 9 - w) % 10], acc[w]);
            }
        }

        // combine j-pair within warp (lane L with L^16), lanes 0-15 store
#pragma unroll
        for (int w = 0; w < 10; w++) {
            float2 f = u2f2(acc[w]);
            f.x += __shfl_xor_sync(0xffffffffu, f.x, 16);
            f.y += __shfl_xor_sync(0xffffffffu, f.y, 16);
            if ((tid & 16) == 0) {
                red[warp][(c * 10 + w) * 2 + 0] = f.x;
                red[warp][(c * 10 + w) * 2 + 1] = f.y;
            }
        }
        __syncthreads();

        // reduce 8 warp-rows over 320 entries, store this batch's partial
        for (int idx = tid; idx < 320; idx += 256) {
            float v = 0.f;
#pragma unroll
            for (int ww = 0; ww < 8; ww++) v += red[ww][idx];
            fpart_g[((size_t)b * 16 + s) * 320 + idx] = v;
        }
        __syncthreads();   // red reused next batch
    }
}

// ---------------- kernel 2: amp + Linear(2C->2) + out filter ----------------
// one block per b, 512 threads. Stage the 20KB fpart slice into smem (float4),
// reduce over s from smem. Writes pre-BN out_g.
__global__ void __launch_bounds__(512) stage23_kernel(const float* __restrict__ Wnl,
                                                      const float* __restrict__ WoR,
                                                      const float* __restrict__ WoI) {
    __shared__ __align__(16) float sbuf[5120];    // 20KB staging
    __shared__ float tf[10][32];       // [w][i], i<16: amp*fr, i>=16: amp*fi
    __shared__ float contrib[10][32];  // [w][c*2+o]

    int b = blockIdx.x;
    int tid = threadIdx.x;

    // bulk stage fpart[b] (5120 floats = 1280 float4) into smem
    {
        const float4* src4 = (const float4*)(fpart_g + (size_t)b * 5120);
        float4* dst4 = (float4*)sbuf;
        if (tid < 256) {
#pragma unroll
            for (int i = 0; i < 5; i++) dst4[tid + i * 256] = src4[tid + i * 256];
        }
    }
    __syncthreads();

    // reduce over s from smem; idx = (c*10+w)*2+o = tid
    if (tid < 320) {
        float v = 0.f;
#pragma unroll
        for (int s = 0; s < 16; s++) v += sbuf[s * 320 + tid];
        float other = __shfl_xor_sync(0xffffffffu, v, 1);
        float amp = v * v + other * other;
        int pair = tid >> 1;          // c*10 + w
        int o    = tid & 1;
        int c    = pair / 10;
        int w    = pair - c * 10;
        tf[w][c + 16 * o] = amp * v;  // o=0: amp*fr ; o=1: amp*fi
    }
    __syncthreads();

    // Linear(2C->2) + output-filter weighting
    if (tid < 320) {
        int w = tid >> 5;
        int q = tid & 31;
        int c = q >> 1;
        int o = q & 1;
        float acc = 0.f;
        const float* wn = Wnl + (c * 2 + o) * 32;
#pragma unroll
        for (int i = 0; i < 32; i++) acc += tf[w][i] * wn[i];
        float wo = (o == 0 ? WoR : WoI)[c * 10 + w];
        contrib[w][q] = acc * wo;
    }
    __syncthreads();

    // sum over w, write pre-BN output
    if (tid < 32) {
        float ssum = 0.f;
#pragma unroll
        for (int ww = 0; ww < 10; ww++) ssum += contrib[ww][tid];
        out_g[b * 32 + tid] = ssum;
    }
}

// ---------------- kernel 3: BatchNorm1d (training stats), 1 block ----------------
__global__ void __launch_bounds__(512) bn_kernel(const float* __restrict__ gamma,
                                                 const float* __restrict__ beta,
                                                 float* __restrict__ out) {
    __shared__ float bnbuf[32][257];   // [q = ch*2+o][b], padded rows

    int tid = threadIdx.x;
    for (int i = tid; i < 8192; i += 512) {
        int bb = i >> 5;
        int q  = i & 31;
        bnbuf[q][bb] = out_g[i];
    }
    __syncthreads();

    // one warp per channel
    int ch = tid >> 5, lane = tid & 31;
    float s1 = 0.f;
#pragma unroll
    for (int j = 0; j < 8; j++) {
        int bb = lane + j * 32;
        s1 += bnbuf[2 * ch][bb] + bnbuf[2 * ch + 1][bb];
    }
#pragma unroll
    for (int off = 16; off; off >>= 1) s1 += __shfl_xor_sync(0xffffffffu, s1, off);
    float mean = s1 * (1.f / 512.f);

    float s2 = 0.f;
#pragma unroll
    for (int j = 0; j < 8; j++) {
        int bb = lane + j * 32;
        float d0 = bnbuf[2 * ch][bb] - mean;
        float d1 = bnbuf[2 * ch + 1][bb] - mean;
        s2 += d0 * d0 + d1 * d1;
    }
#pragma unroll
    for (int off = 16; off; off >>= 1) s2 += __shfl_xor_sync(0xffffffffu, s2, off);
    float inv = rsqrtf(s2 * (1.f / 512.f) + 1e-5f);

    float g = gamma[ch], bb_ = beta[ch];
#pragma unroll
    for (int j = 0; j < 8; j++) {
        int bb = lane + j * 32;
        out[bb * 32 + 2 * ch]     = (bnbuf[2 * ch][bb] - mean) * inv * g + bb_;
        out[bb * 32 + 2 * ch + 1] = (bnbuf[2 * ch + 1][bb] - mean) * inv * g + bb_;
    }
}

// ---------------- launch ----------------
extern "C" void kernel_launch(void* const* d_in, const int* in_sizes, int n_in,
                              void* d_out, int out_size) {
    const float* x     = (const float*)d_in[0];
    const float* wir   = (const float*)d_in[1];
    const float* wii   = (const float*)d_in[2];
    const float* wnl   = (const float*)d_in[3];
    const float* wor   = (const float*)d_in[4];
    const float* woi   = (const float*)d_in[5];
    const float* gamma = (const float*)d_in[6];
    const float* beta  = (const float*)d_in[7];
    float* out = (float*)d_out;

    stage1_kernel<<<dim3(64, 16), 256>>>(x, wir, wii);
    stage23_kernel<<<256, 512>>>(wnl, wor, woi);
    bn_kernel<<<1, 512>>>(gamma, beta, out);
}

// round 11
// speedup vs baseline: 1.9260x; 1.0995x over previous
#include <cuda_runtime.h>

typedef unsigned long long ULL;

// ---------------- device scratch (no allocations allowed) ----------------
// Packed, zero-padded weights: wpad_g[lp][c] = (W_in_real[c][lp-9], W_in_imag[c][lp-9]),
// zero outside l in [0, 4086]. lp in [0, 4105).
__device__ __align__(16) float2 wpad_g[4105 * 16];
// Pre-batchnorm output: [b][c*2+o]
__device__ float out_g[256 * 32];

// ---------------- packed f32x2 FMA (FFMA2) ----------------
__device__ __forceinline__ ULL fma2(ULL a, ULL b, ULL c) {
    ULL d;
    asm("fma.rn.f32x2 %0, %1, %2, %3;" : "=l"(d) : "l"(a), "l"(b), "l"(c));
    return d;
}
__device__ __forceinline__ float2 u2f2(ULL v) {
    return make_float2(__uint_as_float((unsigned)(v & 0xffffffffULL)),
                       __uint_as_float((unsigned)(v >> 32)));
}

// ---------------- kernel 0: pack + pad weights ----------------
__global__ void __launch_bounds__(512) pack_kernel(const float* __restrict__ wr,
                                                   const float* __restrict__ wi) {
    int idx = blockIdx.x * blockDim.x + threadIdx.x;
    if (idx >= 4105 * 16) return;
    int lp = idx >> 4;
    int c  = idx & 15;
    int l  = lp - 9;
    float2 v = make_float2(0.f, 0.f);
    if (l >= 0 && l < 4087) {
        v.x = wr[c * 4087 + l];
        v.y = wi[c * 4087 + l];
    }
    wpad_g[lp * 16 + c] = v;
}

// ---------------- kernel 1: FUSED stage1+2+3 — one block per batch ----------------
// 1024 threads = 16 channels x 64 j-chunks; thread (c,j) accumulates its
// contiguous 64-position run into acc[10] registers (xv[8] batches, MLP 8,
// no barriers in the mainloop; weights LDG.64 from L2-resident wpad_g with a
// 10-deep rotating register window). Then: shfl j-pair combine -> 32x320 smem
// reduce -> amp -> per-channel Linear(2C->2) -> output filter -> out_g[b][32].
// f[b,w,c] = sum_p x[b,p,c] * Wpad[p + 9 - w]
__global__ void __launch_bounds__(1024) fused_kernel(const float* __restrict__ x,
                                                     const float* __restrict__ Wnl,
                                                     const float* __restrict__ WoR,
                                                     const float* __restrict__ WoI) {
    __shared__ float red[32][320];     // 40KB: per-warp partials
    __shared__ float tf[10][32];       // [w][i], i<16: amp*fr, i>=16: amp*fi
    __shared__ float contrib[10][32];  // [w][c*2+o]

    int b    = blockIdx.x;
    int tid  = threadIdx.x;
    int c    = tid & 15;
    int j    = tid >> 4;               // 0..63
    int p0   = j * 64;
    int warp = tid >> 5;               // 0..31

    const ULL* xp = (const ULL*)x + ((size_t)b * 4096 + p0) * 16 + c;
    const ULL* wp = (const ULL*)wpad_g + (size_t)p0 * 16 + c;   // wp[k*16] = Wpad[p0+k]

    // rotating window: slot m%10 holds Wpad[p0+m]; preload m = 0..8
    ULL wbuf[10];
#pragma unroll
    for (int k = 0; k < 9; k++) wbuf[k] = wp[(size_t)k * 16];

    ULL acc[10];
#pragma unroll
    for (int w = 0; w < 10; w++) acc[w] = 0ULL;

    // 8 chunks of 8 positions; x loads batched up front (MLP 8); all indices static
#pragma unroll
    for (int ch = 0; ch < 8; ch++) {
        ULL xv[8];
#pragma unroll
        for (int u = 0; u < 8; u++) xv[u] = xp[(size_t)(ch * 8 + u) * 16];
#pragma unroll
        for (int u = 0; u < 8; u++) {
            int t = ch * 8 + u;
            wbuf[(t + 9) % 10] = wp[(size_t)(t + 9) * 16];   // Wpad[p0+t+9]
#pragma unroll
            for (int w = 0; w < 10; w++)
                acc[w] = fma2(xv[u], wbuf[(t + 9 - w) % 10], acc[w]);   // Wpad[p+9-w]
        }
    }

    // combine j-pair within warp (lane L with L^16); lanes 0-15 hold (c, j-pair)
#pragma unroll
    for (int w = 0; w < 10; w++) {
        float2 f = u2f2(acc[w]);
        f.x += __shfl_xor_sync(0xffffffffu, f.x, 16);
        f.y += __shfl_xor_sync(0xffffffffu, f.y, 16);
        if ((tid & 16) == 0) {
            red[warp][(c * 10 + w) * 2 + 0] = f.x;
            red[warp][(c * 10 + w) * 2 + 1] = f.y;
        }
    }
    __syncthreads();

    // reduce 32 warp-rows -> f; amp nonlinearity (pairs adjacent: o = tid&1)
    if (tid < 320) {
        float v = 0.f;
#pragma unroll
        for (int r = 0; r < 32; r++) v += red[r][tid];   // stride 320 ≡ 0 mod 32: conflict-free
        float other = __shfl_xor_sync(0xffffffffu, v, 1);
        float amp = v * v + other * other;
        int pair = tid >> 1;          // c*10 + w
        int o    = tid & 1;
        int cc   = pair / 10;
        int w    = pair - cc * 10;
        tf[w][cc + 16 * o] = amp * v; // o=0: amp*fr ; o=1: amp*fi
    }
    __syncthreads();

    // per-channel Linear(2C->2) + output-filter weighting
    if (tid < 320) {
        int w = tid >> 5;
        int q = tid & 31;
        int cc = q >> 1;
        int o  = q & 1;
        float acc2 = 0.f;
        const float* wn = Wnl + (cc * 2 + o) * 32;
#pragma unroll
        for (int i = 0; i < 32; i++) acc2 += tf[w][i] * wn[i];
        float wo = (o == 0 ? WoR : WoI)[cc * 10 + w];
        contrib[w][q] = acc2 * wo;
    }
    __syncthreads();

    // sum over w, write pre-BN output
    if (tid < 32) {
        float ssum = 0.f;
#pragma unroll
        for (int ww = 0; ww < 10; ww++) ssum += contrib[ww][tid];
        out_g[b * 32 + tid] = ssum;
    }
}

// ---------------- kernel 2: BatchNorm1d (training stats), 1 block ----------------
__global__ void __launch_bounds__(512) bn_kernel(const float* __restrict__ gamma,
                                                 const float* __restrict__ beta,
                                                 float* __restrict__ out) {
    __shared__ float bnbuf[32][257];   // [q = ch*2+o][b], padded rows

    int tid = threadIdx.x;
    for (int i = tid; i < 8192; i += 512) {
        int bb = i >> 5;
        int q  = i & 31;
        bnbuf[q][bb] = out_g[i];
    }
    __syncthreads();

    // one warp per channel
    int ch = tid >> 5, lane = tid & 31;
    float s1 = 0.f;
#pragma unroll
    for (int j = 0; j < 8; j++) {
        int bb = lane + j * 32;
        s1 += bnbuf[2 * ch][bb] + bnbuf[2 * ch + 1][bb];
    }
#pragma unroll
    for (int off = 16; off; off >>= 1) s1 += __shfl_xor_sync(0xffffffffu, s1, off);
    float mean = s1 * (1.f / 512.f);

    float s2 = 0.f;
#pragma unroll
    for (int j = 0; j < 8; j++) {
        int bb = lane + j * 32;
        float d0 = bnbuf[2 * ch][bb] - mean;
        float d1 = bnbuf[2 * ch + 1][bb] - mean;
        s2 += d0 * d0 + d1 * d1;
    }
#pragma unroll
    for (int off = 16; off; off >>= 1) s2 += __shfl_xor_sync(0xffffffffu, s2, off);
    float inv = rsqrtf(s2 * (1.f / 512.f) + 1e-5f);

    float g = gamma[ch], bb_ = beta[ch];
#pragma unroll
    for (int j = 0; j < 8; j++) {
        int bb = lane + j * 32;
        out[bb * 32 + 2 * ch]     = (bnbuf[2 * ch][bb] - mean) * inv * g + bb_;
        out[bb * 32 + 2 * ch + 1] = (bnbuf[2 * ch + 1][bb] - mean) * inv * g + bb_;
    }
}

// ---------------- launch ----------------
extern "C" void kernel_launch(void* const* d_in, const int* in_sizes, int n_in,
                              void* d_out, int out_size) {
    const float* x     = (const float*)d_in[0];
    const float* wir   = (const float*)d_in[1];
    const float* wii   = (const float*)d_in[2];
    const float* wnl   = (const float*)d_in[3];
    const float* wor   = (const float*)d_in[4];
    const float* woi   = (const float*)d_in[5];
    const float* gamma = (const float*)d_in[6];
    const float* beta  = (const float*)d_in[7];
    float* out = (float*)d_out;

    pack_kernel<<<(4105 * 16 + 511) / 512, 512>>>(wir, wii);
    fused_kernel<<<256, 1024>>>(x, wnl, wor, woi);
    bn_kernel<<<1, 512>>>(gamma, beta, out);
}